// round 1
// baseline (speedup 1.0000x reference)
#include <cuda_runtime.h>
#include <math.h>

#define BB 4
#define LL 2048
#define DD 1024
#define HH 16
#define KK 256
#define DH 64
#define MROWS (BB*LL)   // 8192

// ---- scratch (device globals; no runtime allocation allowed) ----
__device__ float g_q[BB*LL*DD];        // x @ Wq^T        [B,L,D]
__device__ float g_xk[BB*LL*DD];       // x @ Wk^T        [B,L,D]
__device__ float g_xv[BB*LL*DD];       // x @ Wv^T        [B,L,D]
__device__ float g_keys_t[BB*DD*KK];   // keys transposed [B,D,K]
__device__ float g_vals[BB*KK*DD];     // vals            [B,K,D]
__device__ float g_ctx[BB*LL*DD];      // attention out   [B,L,D]

// ============================================================
// GEMM NT: C[m,n] = sum_k A[m,k] * B[n,k]  (+ bias[n] optional)
// A: [M,Kd] row-major, B: [N,Kd] row-major. 128x128 tile, BK=16.
// ============================================================
template<bool BIAS>
__global__ __launch_bounds__(256)
void gemm_nt(const float* __restrict__ A, const float* __restrict__ Bm,
             const float* __restrict__ bias, float* __restrict__ C,
             int M, int N, int Kd)
{
    __shared__ float As[16][132];
    __shared__ float Bs[16][132];
    const int m0 = blockIdx.y * 128;
    const int n0 = blockIdx.x * 128;
    const int tid = threadIdx.x;
    const int tx = tid & 15, ty = tid >> 4;

    float acc[8][8] = {};

    for (int k0 = 0; k0 < Kd; k0 += 16) {
        #pragma unroll
        for (int t = 0; t < 2; t++) {
            int id  = tid + t * 256;          // 0..511
            int row = id >> 2;                // 0..127
            int kg  = (id & 3) * 4;           // 0,4,8,12
            float4 va = *(const float4*)&A [(size_t)(m0 + row) * Kd + k0 + kg];
            As[kg+0][row] = va.x; As[kg+1][row] = va.y;
            As[kg+2][row] = va.z; As[kg+3][row] = va.w;
            float4 vb = *(const float4*)&Bm[(size_t)(n0 + row) * Kd + k0 + kg];
            Bs[kg+0][row] = vb.x; Bs[kg+1][row] = vb.y;
            Bs[kg+2][row] = vb.z; Bs[kg+3][row] = vb.w;
        }
        __syncthreads();
        #pragma unroll
        for (int kk = 0; kk < 16; kk++) {
            float a[8], b[8];
            *(float4*)&a[0] = *(const float4*)&As[kk][ty*8];
            *(float4*)&a[4] = *(const float4*)&As[kk][ty*8+4];
            *(float4*)&b[0] = *(const float4*)&Bs[kk][tx*8];
            *(float4*)&b[4] = *(const float4*)&Bs[kk][tx*8+4];
            #pragma unroll
            for (int i = 0; i < 8; i++)
                #pragma unroll
                for (int j = 0; j < 8; j++)
                    acc[i][j] += a[i] * b[j];
        }
        __syncthreads();
    }

    #pragma unroll
    for (int i = 0; i < 8; i++) {
        int m = m0 + ty*8 + i;
        #pragma unroll
        for (int j = 0; j < 8; j += 4) {
            int n = n0 + tx*8 + j;
            float4 v;
            v.x = acc[i][j+0]; v.y = acc[i][j+1];
            v.z = acc[i][j+2]; v.w = acc[i][j+3];
            if (BIAS) {
                float4 bv = *(const float4*)&bias[n];
                v.x += bv.x; v.y += bv.y; v.z += bv.z; v.w += bv.w;
            }
            *(float4*)&C[(size_t)m * N + n] = v;
        }
    }
}

// ============================================================
// GEMM TN (batched over z): C[m,n] = sum_l A[l*lda + m] * B[l*ldb + n]
// Inner dim = Lin (2048). 128x128 tile, BK=16.
// ============================================================
__global__ __launch_bounds__(256)
void gemm_tn(const float* __restrict__ A, long Abatch, int lda,
             const float* __restrict__ Bm, long Bbatch, int ldb,
             float* __restrict__ C, long Cbatch, int ldc,
             int M, int N, int Lin)
{
    __shared__ float As[16][132];
    __shared__ float Bs[16][132];
    const int bz = blockIdx.z;
    A  += (size_t)bz * Abatch;
    Bm += (size_t)bz * Bbatch;
    C  += (size_t)bz * Cbatch;

    const int m0 = blockIdx.y * 128;
    const int n0 = blockIdx.x * 128;
    const int tid = threadIdx.x;
    const int tx = tid & 15, ty = tid >> 4;

    float acc[8][8] = {};

    for (int l0 = 0; l0 < Lin; l0 += 16) {
        #pragma unroll
        for (int t = 0; t < 2; t++) {
            int id = tid + t * 256;       // 0..511
            int kk = id >> 5;             // 0..15
            int mj = (id & 31) * 4;       // 0..124
            *(float4*)&As[kk][mj] = *(const float4*)&A [(size_t)(l0 + kk) * lda + m0 + mj];
            *(float4*)&Bs[kk][mj] = *(const float4*)&Bm[(size_t)(l0 + kk) * ldb + n0 + mj];
        }
        __syncthreads();
        #pragma unroll
        for (int kk = 0; kk < 16; kk++) {
            float a[8], b[8];
            *(float4*)&a[0] = *(const float4*)&As[kk][ty*8];
            *(float4*)&a[4] = *(const float4*)&As[kk][ty*8+4];
            *(float4*)&b[0] = *(const float4*)&Bs[kk][tx*8];
            *(float4*)&b[4] = *(const float4*)&Bs[kk][tx*8+4];
            #pragma unroll
            for (int i = 0; i < 8; i++)
                #pragma unroll
                for (int j = 0; j < 8; j++)
                    acc[i][j] += a[i] * b[j];
        }
        __syncthreads();
    }

    #pragma unroll
    for (int i = 0; i < 8; i++) {
        int m = m0 + ty*8 + i;
        #pragma unroll
        for (int j = 0; j < 8; j += 4) {
            int n = n0 + tx*8 + j;
            float4 v;
            v.x = acc[i][j+0]; v.y = acc[i][j+1];
            v.z = acc[i][j+2]; v.w = acc[i][j+3];
            *(float4*)&C[(size_t)m * ldc + n] = v;
        }
    }
}

// ============================================================
// Attention: one CTA per (b, h, 64-row l-tile).
// smem: Qs[64][68], Ks[64][264] (kd,col), Vs[256][68] (col,dh), Ps[64][264]
// ============================================================
#define QS_STRIDE 68
#define KS_STRIDE 264
#define VS_STRIDE 68
#define PS_STRIDE 264
#define ATTN_SMEM ((64*QS_STRIDE + 64*KS_STRIDE + 256*VS_STRIDE + 64*PS_STRIDE) * 4)

__global__ __launch_bounds__(256)
void attn_kernel()
{
    extern __shared__ float sm[];
    float* Qs = sm;                         // [64][68]
    float* Ks = Qs + 64*QS_STRIDE;          // [64][264]  kd-major
    float* Vs = Ks + 64*KS_STRIDE;          // [256][68]  col-major
    float* Ps = Vs + 256*VS_STRIDE;         // [64][264]

    const int b  = blockIdx.z;
    const int h  = blockIdx.y;
    const int l0 = blockIdx.x * 64;
    const int tid = threadIdx.x;

    // ---- fill Qs (apply the "plain reshape" gather) ----
    #pragma unroll
    for (int it = 0; it < 4; it++) {
        int idx = tid + it * 256;           // 0..1023
        int r  = idx >> 4;
        int dq = (idx & 15) * 4;
        int l  = l0 + r;
        const float* src = g_q + ((size_t)(b * LL) + h * 128 + (l >> 4)) * DD
                               + (l & 15) * DH + dq;
        *(float4*)&Qs[r * QS_STRIDE + dq] = *(const float4*)src;
    }
    // ---- fill Ks[kd][col] from keys_t[b][h*64+kd][col] (natural layout) ----
    #pragma unroll
    for (int it = 0; it < 16; it++) {
        int idx = tid + it * 256;           // 0..4095
        int kd = idx >> 6;
        int c4 = (idx & 63) * 4;
        *(float4*)&Ks[kd * KS_STRIDE + c4] =
            *(const float4*)&g_keys_t[((size_t)b * DD + h * DH + kd) * KK + c4];
    }
    // ---- fill Vs[col][dh] from vals[b][col][h*64+dh] ----
    #pragma unroll
    for (int it = 0; it < 16; it++) {
        int idx = tid + it * 256;
        int col = idx >> 4;
        int dq  = (idx & 15) * 4;
        *(float4*)&Vs[col * VS_STRIDE + dq] =
            *(const float4*)&g_vals[((size_t)b * KK + col) * DD + h * DH + dq];
    }
    __syncthreads();

    // ---- S = Q K^T : warp wy -> rows wy*8..+7 ; lane tx -> cols tx*8..+7 ----
    const int tx = tid & 31, wy = tid >> 5;
    float acc[8][8] = {};
    #pragma unroll 4
    for (int kd = 0; kd < 64; kd++) {
        float a[8], bq[8];
        #pragma unroll
        for (int i = 0; i < 8; i++) a[i] = Qs[(wy*8 + i) * QS_STRIDE + kd];
        *(float4*)&bq[0] = *(const float4*)&Ks[kd * KS_STRIDE + tx*8];
        *(float4*)&bq[4] = *(const float4*)&Ks[kd * KS_STRIDE + tx*8 + 4];
        #pragma unroll
        for (int i = 0; i < 8; i++)
            #pragma unroll
            for (int j = 0; j < 8; j++)
                acc[i][j] += a[i] * bq[j];
    }

    // ---- softmax (scale, rowwise over 256 via warp shuffle) -> Ps ----
    const float SCALE = 0.125f;  // 64^-0.5
    #pragma unroll
    for (int i = 0; i < 8; i++) {
        float mx = -1e30f;
        #pragma unroll
        for (int j = 0; j < 8; j++) {
            acc[i][j] *= SCALE;
            mx = fmaxf(mx, acc[i][j]);
        }
        #pragma unroll
        for (int o = 16; o > 0; o >>= 1)
            mx = fmaxf(mx, __shfl_xor_sync(0xffffffffu, mx, o));
        float s = 0.f;
        #pragma unroll
        for (int j = 0; j < 8; j++) {
            acc[i][j] = __expf(acc[i][j] - mx);
            s += acc[i][j];
        }
        #pragma unroll
        for (int o = 16; o > 0; o >>= 1)
            s += __shfl_xor_sync(0xffffffffu, s, o);
        float inv = 1.f / s;
        float4 p0, p1;
        p0.x = acc[i][0]*inv; p0.y = acc[i][1]*inv; p0.z = acc[i][2]*inv; p0.w = acc[i][3]*inv;
        p1.x = acc[i][4]*inv; p1.y = acc[i][5]*inv; p1.z = acc[i][6]*inv; p1.w = acc[i][7]*inv;
        *(float4*)&Ps[(wy*8 + i) * PS_STRIDE + tx*8    ] = p0;
        *(float4*)&Ps[(wy*8 + i) * PS_STRIDE + tx*8 + 4] = p1;
    }
    __syncthreads();

    // ---- O = P V : rows wy*8..+7, lane covers d = tx*2, tx*2+1 ----
    float o0[8] = {}, o1[8] = {};
    #pragma unroll 4
    for (int j = 0; j < 256; j++) {
        float2 v = *(const float2*)&Vs[j * VS_STRIDE + tx*2];
        #pragma unroll
        for (int i = 0; i < 8; i++) {
            float p = Ps[(wy*8 + i) * PS_STRIDE + j];
            o0[i] += p * v.x;
            o1[i] += p * v.y;
        }
    }
    #pragma unroll
    for (int i = 0; i < 8; i++) {
        int l = l0 + wy*8 + i;
        float2 st; st.x = o0[i]; st.y = o1[i];
        *(float2*)&g_ctx[((size_t)(b * LL) + l) * DD + h * DH + tx*2] = st;
    }
}

// ============================================================
extern "C" void kernel_launch(void* const* d_in, const int* in_sizes, int n_in,
                              void* d_out, int out_size)
{
    const float* x      = (const float*)d_in[0];
    const float* Wq     = (const float*)d_in[1];
    const float* Wk     = (const float*)d_in[2];
    const float* Wv     = (const float*)d_in[3];
    const float* proj_k = (const float*)d_in[4];
    const float* proj_v = (const float*)d_in[5];
    const float* Wo     = (const float*)d_in[6];
    const float* bo     = (const float*)d_in[7];
    float* out = (float*)d_out;

    float *q, *xk, *xv, *keys_t, *vals, *ctx;
    cudaGetSymbolAddress((void**)&q,      g_q);
    cudaGetSymbolAddress((void**)&xk,     g_xk);
    cudaGetSymbolAddress((void**)&xv,     g_xv);
    cudaGetSymbolAddress((void**)&keys_t, g_keys_t);
    cudaGetSymbolAddress((void**)&vals,   g_vals);
    cudaGetSymbolAddress((void**)&ctx,    g_ctx);

    cudaFuncSetAttribute(attn_kernel, cudaFuncAttributeMaxDynamicSharedMemorySize, ATTN_SMEM);

    dim3 grid_nt(DD / 128, MROWS / 128);   // (8, 64)

    // q / xk / xv = x @ W^T
    gemm_nt<false><<<grid_nt, 256>>>(x, Wq, nullptr, q,  MROWS, DD, DD);
    gemm_nt<false><<<grid_nt, 256>>>(x, Wk, nullptr, xk, MROWS, DD, DD);
    gemm_nt<false><<<grid_nt, 256>>>(x, Wv, nullptr, xv, MROWS, DD, DD);

    // keys_t[b][d][kcol] = sum_l xk[b][l][d] * proj_k[l][kcol]   (M=D, N=K)
    gemm_tn<<<dim3(KK / 128, DD / 128, BB), 256>>>(
        xk, (long)LL * DD, DD,
        proj_k, 0, KK,
        keys_t, (long)DD * KK, KK,
        DD, KK, LL);

    // vals[b][kcol][d] = sum_l proj_v[l][kcol] * xv[b][l][d]     (M=K, N=D)
    gemm_tn<<<dim3(DD / 128, KK / 128, BB), 256>>>(
        proj_v, 0, KK,
        xv, (long)LL * DD, DD,
        vals, (long)KK * DD, DD,
        KK, DD, LL);

    // attention core
    attn_kernel<<<dim3(LL / 64, HH, BB), 256, ATTN_SMEM>>>();

    // out = ctx @ Wo^T + bo
    gemm_nt<true><<<grid_nt, 256>>>(ctx, Wo, bo, out, MROWS, DD, DD);
}

// round 3
// speedup vs baseline: 2.3340x; 2.3340x over previous
#include <cuda_runtime.h>
#include <cuda_fp16.h>
#include <cstdint>
#include <math.h>

#define BB 4
#define LL 2048
#define DD 1024
#define HH 16
#define KK 256
#define DH 64
#define MROWS (BB*LL)   // 8192

// ---- scratch (device globals; no runtime allocation allowed) ----
__device__ float g_q[BB*LL*DD];        // x @ Wq^T            [B,L,D]
__device__ float g_xkt[BB*DD*LL];      // (x @ Wk^T)^T        [B,D,L]
__device__ float g_xvt[BB*DD*LL];      // (x @ Wv^T)^T        [B,D,L]
__device__ float g_projkt[KK*LL];      // proj_k^T            [K,L]
__device__ float g_projvt[KK*LL];      // proj_v^T            [K,L]
__device__ float g_keys_t[BB*DD*KK];   // keys transposed     [B,D,K]
__device__ float g_vals[BB*KK*DD];     // vals                [B,K,D]
__device__ float g_ctx[BB*LL*DD];      // attention out       [B,L,D]

// ============================================================
// mma.sync helpers (baseline PTX, works on compute_103)
// ============================================================
__device__ __forceinline__ uint32_t smem_u32(const void* p) {
    uint32_t a;
    asm("{ .reg .u64 t; cvta.to.shared.u64 t, %1; cvt.u32.u64 %0, t; }"
        : "=r"(a) : "l"(p));
    return a;
}
__device__ __forceinline__ void ldsm4(uint32_t* r, uint32_t addr) {
    asm volatile("ldmatrix.sync.aligned.m8n8.x4.shared.b16 {%0,%1,%2,%3}, [%4];"
        : "=r"(r[0]), "=r"(r[1]), "=r"(r[2]), "=r"(r[3]) : "r"(addr));
}
__device__ __forceinline__ void ldsm2(uint32_t* r, uint32_t addr) {
    asm volatile("ldmatrix.sync.aligned.m8n8.x2.shared.b16 {%0,%1}, [%2];"
        : "=r"(r[0]), "=r"(r[1]) : "r"(addr));
}
__device__ __forceinline__ void mma16816(float* c, const uint32_t* a, const uint32_t* b) {
    asm volatile(
        "mma.sync.aligned.m16n8k16.row.col.f32.f16.f16.f32 "
        "{%0,%1,%2,%3}, {%4,%5,%6,%7}, {%8,%9}, {%0,%1,%2,%3};"
        : "+f"(c[0]), "+f"(c[1]), "+f"(c[2]), "+f"(c[3])
        : "r"(a[0]), "r"(a[1]), "r"(a[2]), "r"(a[3]), "r"(b[0]), "r"(b[1]));
}

// ============================================================
// split-fp16 NT-GEMM:  C[m,n] = sum_k A[m,k]*B[n,k]  (+bias[n])
// A ~ A_hi + A_lo, B ~ B_hi + B_lo (fp16 pairs);
// C = Ah*Bh + Ah*Bl + Al*Bh  (error ~2^-22).
// CTA tile 128x128, BK=32. 8 warps, warp tile 64x32.
// Double-buffered smem; register-staged gmem prefetch.
// ============================================================
#define TPAD 40                  // half stride per smem row (32 + 8 pad)
#define TSZ  (128*TPAD)          // halves per tile
#define GEMM_SMEM (8*TSZ*2)      // 4 tiles x 2 stages x 2B = 81920

template<bool BIAS>
__global__ __launch_bounds__(256, 1)
void gemm_fp16x2(const float* __restrict__ A, long Ab, int lda,
                 const float* __restrict__ B, long Bb, int ldb,
                 float* __restrict__ C, long Cb, int ldc,
                 const float* __restrict__ bias, int Kd)
{
    extern __shared__ __align__(16) char smc[];
    __half* sm = (__half*)smc;

    const int tid  = threadIdx.x;
    const int lane = tid & 31;
    const int wid  = tid >> 5;
    const int wm   = wid >> 2;          // 0..1
    const int wn   = wid & 3;           // 0..3
    const int g    = lane >> 2;         // 0..7
    const int tig  = lane & 3;          // 0..3

    A += (size_t)blockIdx.z * Ab;
    B += (size_t)blockIdx.z * Bb;
    C += (size_t)blockIdx.z * Cb;
    const int m0 = blockIdx.y * 128;
    const int n0 = blockIdx.x * 128;

    const float* Aip = A + (size_t)m0 * lda;
    const float* Bip = B + (size_t)n0 * ldb;

    float acc[4][4][4];
    #pragma unroll
    for (int i = 0; i < 4; i++)
        #pragma unroll
        for (int j = 0; j < 4; j++)
            #pragma unroll
            for (int v = 0; v < 4; v++) acc[i][j][v] = 0.f;

    const int ldRow = tid >> 3;          // 0..31 per 256... (idx>>3 below)
    (void)ldRow;

    float4 ra[4], rb[4];

    // ---- load stage regs for iteration `it` ----
    auto load_regs = [&](int it) {
        const int k0 = it * 32;
        #pragma unroll
        for (int p = 0; p < 4; p++) {
            int idx = tid + p * 256;
            int row = idx >> 3;
            int cc  = (idx & 7) * 4;
            ra[p] = *(const float4*)(Aip + (size_t)row * lda + k0 + cc);
            rb[p] = *(const float4*)(Bip + (size_t)row * ldb + k0 + cc);
        }
    };

    // ---- convert + store regs into smem stage s ----
    auto store_tiles = [&](int s) {
        __half* A_hi = sm + s * 4 * TSZ;
        __half* A_lo = A_hi + TSZ;
        __half* B_hi = A_lo + TSZ;
        __half* B_lo = B_hi + TSZ;
        #pragma unroll
        for (int p = 0; p < 4; p++) {
            int idx = tid + p * 256;
            int row = idx >> 3;
            int cc  = (idx & 7) * 4;
            {
                float4 v = ra[p];
                __half2 h0 = __floats2half2_rn(v.x, v.y);
                __half2 h1 = __floats2half2_rn(v.z, v.w);
                float2 f0 = __half22float2(h0);
                float2 f1 = __half22float2(h1);
                __half2 l0 = __floats2half2_rn(v.x - f0.x, v.y - f0.y);
                __half2 l1 = __floats2half2_rn(v.z - f1.x, v.w - f1.y);
                uint2 hw, lw;
                hw.x = *(uint32_t*)&h0; hw.y = *(uint32_t*)&h1;
                lw.x = *(uint32_t*)&l0; lw.y = *(uint32_t*)&l1;
                *(uint2*)(A_hi + row * TPAD + cc) = hw;
                *(uint2*)(A_lo + row * TPAD + cc) = lw;
            }
            {
                float4 v = rb[p];
                __half2 h0 = __floats2half2_rn(v.x, v.y);
                __half2 h1 = __floats2half2_rn(v.z, v.w);
                float2 f0 = __half22float2(h0);
                float2 f1 = __half22float2(h1);
                __half2 l0 = __floats2half2_rn(v.x - f0.x, v.y - f0.y);
                __half2 l1 = __floats2half2_rn(v.z - f1.x, v.w - f1.y);
                uint2 hw, lw;
                hw.x = *(uint32_t*)&h0; hw.y = *(uint32_t*)&h1;
                lw.x = *(uint32_t*)&l0; lw.y = *(uint32_t*)&l1;
                *(uint2*)(B_hi + row * TPAD + cc) = hw;
                *(uint2*)(B_lo + row * TPAD + cc) = lw;
            }
        }
    };

    // ---- compute on stage s ----
    auto compute = [&](int s) {
        const uint32_t aHi = smem_u32(sm + s * 4 * TSZ);
        const uint32_t aLo = aHi + TSZ * 2;
        const uint32_t bHi = aLo + TSZ * 2;
        const uint32_t bLo = bHi + TSZ * 2;

        #pragma unroll
        for (int ks = 0; ks < 2; ks++) {
            uint32_t ah[4][4], al[4][4], bh[4][2], bl[4][2];
            const int acol = ks * 16 + (lane >> 4) * 8;
            #pragma unroll
            for (int mi = 0; mi < 4; mi++) {
                int r = wm * 64 + mi * 16 + (lane & 15);
                uint32_t off = (uint32_t)(r * TPAD + acol) * 2;
                ldsm4(ah[mi], aHi + off);
                ldsm4(al[mi], aLo + off);
            }
            const int bcol = ks * 16 + ((lane >> 3) & 1) * 8;
            #pragma unroll
            for (int ni = 0; ni < 4; ni++) {
                int r = wn * 32 + ni * 8 + (lane & 7);
                uint32_t off = (uint32_t)(r * TPAD + bcol) * 2;
                ldsm2(bh[ni], bHi + off);
                ldsm2(bl[ni], bLo + off);
            }
            #pragma unroll
            for (int mi = 0; mi < 4; mi++)
                #pragma unroll
                for (int ni = 0; ni < 4; ni++) {
                    mma16816(acc[mi][ni], ah[mi], bh[ni]);
                    mma16816(acc[mi][ni], ah[mi], bl[ni]);
                    mma16816(acc[mi][ni], al[mi], bh[ni]);
                }
        }
    };

    // ---- pipeline ----
    const int iters = Kd / 32;
    load_regs(0);
    store_tiles(0);
    __syncthreads();
    for (int it = 0; it < iters; it++) {
        const int s = it & 1;
        const bool more = (it + 1 < iters);
        if (more) load_regs(it + 1);
        compute(s);
        if (more) { store_tiles(s ^ 1); __syncthreads(); }
    }

    // ---- epilogue: fp32 stores ----
    #pragma unroll
    for (int mi = 0; mi < 4; mi++) {
        const int r0 = m0 + wm * 64 + mi * 16 + g;
        #pragma unroll
        for (int ni = 0; ni < 4; ni++) {
            const int col = n0 + wn * 32 + ni * 8 + tig * 2;
            float2 v0, v1;
            v0.x = acc[mi][ni][0]; v0.y = acc[mi][ni][1];
            v1.x = acc[mi][ni][2]; v1.y = acc[mi][ni][3];
            if (BIAS) {
                float2 bv = *(const float2*)(bias + col);
                v0.x += bv.x; v0.y += bv.y;
                v1.x += bv.x; v1.y += bv.y;
            }
            *(float2*)(C + (size_t)r0 * ldc + col) = v0;
            *(float2*)(C + (size_t)(r0 + 8) * ldc + col) = v1;
        }
    }
}

// ============================================================
// proj transpose: [L,K] -> [K,L]  (z=0: proj_k, z=1: proj_v)
// ============================================================
__global__ __launch_bounds__(256)
void transpose_proj(const float* __restrict__ pk, const float* __restrict__ pv,
                    float* __restrict__ okt, float* __restrict__ ovt)
{
    __shared__ float t[32][33];
    const float* src = blockIdx.z ? pv : pk;
    float* dst       = blockIdx.z ? ovt : okt;
    int k0 = blockIdx.x * 32, l0 = blockIdx.y * 32;
    int tx = threadIdx.x, ty = threadIdx.y;
    #pragma unroll
    for (int i = 0; i < 32; i += 8)
        t[ty + i][tx] = src[(size_t)(l0 + ty + i) * KK + k0 + tx];
    __syncthreads();
    #pragma unroll
    for (int i = 0; i < 32; i += 8)
        dst[(size_t)(k0 + ty + i) * LL + l0 + tx] = t[tx][ty + i];
}

// ============================================================
// Attention (R1-verified, fp32 SIMT): one CTA per (b,h,64-row tile)
// ============================================================
#define QS_STRIDE 68
#define KS_STRIDE 264
#define VS_STRIDE 68
#define PS_STRIDE 264
#define ATTN_SMEM ((64*QS_STRIDE + 64*KS_STRIDE + 256*VS_STRIDE + 64*PS_STRIDE) * 4)

__global__ __launch_bounds__(256)
void attn_kernel()
{
    extern __shared__ float smf[];
    float* Qs = smf;
    float* Ks = Qs + 64*QS_STRIDE;
    float* Vs = Ks + 64*KS_STRIDE;
    float* Ps = Vs + 256*VS_STRIDE;

    const int b  = blockIdx.z;
    const int h  = blockIdx.y;
    const int l0 = blockIdx.x * 64;
    const int tid = threadIdx.x;

    #pragma unroll
    for (int it = 0; it < 4; it++) {
        int idx = tid + it * 256;
        int r  = idx >> 4;
        int dq = (idx & 15) * 4;
        int l  = l0 + r;
        const float* src = g_q + ((size_t)(b * LL) + h * 128 + (l >> 4)) * DD
                               + (l & 15) * DH + dq;
        *(float4*)&Qs[r * QS_STRIDE + dq] = *(const float4*)src;
    }
    #pragma unroll
    for (int it = 0; it < 16; it++) {
        int idx = tid + it * 256;
        int kd = idx >> 6;
        int c4 = (idx & 63) * 4;
        *(float4*)&Ks[kd * KS_STRIDE + c4] =
            *(const float4*)&g_keys_t[((size_t)b * DD + h * DH + kd) * KK + c4];
    }
    #pragma unroll
    for (int it = 0; it < 16; it++) {
        int idx = tid + it * 256;
        int col = idx >> 4;
        int dq  = (idx & 15) * 4;
        *(float4*)&Vs[col * VS_STRIDE + dq] =
            *(const float4*)&g_vals[((size_t)b * KK + col) * DD + h * DH + dq];
    }
    __syncthreads();

    const int tx = tid & 31, wy = tid >> 5;
    float acc[8][8] = {};
    #pragma unroll 4
    for (int kd = 0; kd < 64; kd++) {
        float a[8], bq[8];
        #pragma unroll
        for (int i = 0; i < 8; i++) a[i] = Qs[(wy*8 + i) * QS_STRIDE + kd];
        *(float4*)&bq[0] = *(const float4*)&Ks[kd * KS_STRIDE + tx*8];
        *(float4*)&bq[4] = *(const float4*)&Ks[kd * KS_STRIDE + tx*8 + 4];
        #pragma unroll
        for (int i = 0; i < 8; i++)
            #pragma unroll
            for (int j = 0; j < 8; j++)
                acc[i][j] += a[i] * bq[j];
    }

    const float SCALE = 0.125f;
    #pragma unroll
    for (int i = 0; i < 8; i++) {
        float mx = -1e30f;
        #pragma unroll
        for (int j = 0; j < 8; j++) {
            acc[i][j] *= SCALE;
            mx = fmaxf(mx, acc[i][j]);
        }
        #pragma unroll
        for (int o = 16; o > 0; o >>= 1)
            mx = fmaxf(mx, __shfl_xor_sync(0xffffffffu, mx, o));
        float s = 0.f;
        #pragma unroll
        for (int j = 0; j < 8; j++) {
            acc[i][j] = __expf(acc[i][j] - mx);
            s += acc[i][j];
        }
        #pragma unroll
        for (int o = 16; o > 0; o >>= 1)
            s += __shfl_xor_sync(0xffffffffu, s, o);
        float inv = 1.f / s;
        float4 p0, p1;
        p0.x = acc[i][0]*inv; p0.y = acc[i][1]*inv; p0.z = acc[i][2]*inv; p0.w = acc[i][3]*inv;
        p1.x = acc[i][4]*inv; p1.y = acc[i][5]*inv; p1.z = acc[i][6]*inv; p1.w = acc[i][7]*inv;
        *(float4*)&Ps[(wy*8 + i) * PS_STRIDE + tx*8    ] = p0;
        *(float4*)&Ps[(wy*8 + i) * PS_STRIDE + tx*8 + 4] = p1;
    }
    __syncthreads();

    float o0[8] = {}, o1[8] = {};
    #pragma unroll 4
    for (int j = 0; j < 256; j++) {
        float2 v = *(const float2*)&Vs[j * VS_STRIDE + tx*2];
        #pragma unroll
        for (int i = 0; i < 8; i++) {
            float p = Ps[(wy*8 + i) * PS_STRIDE + j];
            o0[i] += p * v.x;
            o1[i] += p * v.y;
        }
    }
    #pragma unroll
    for (int i = 0; i < 8; i++) {
        int l = l0 + wy*8 + i;
        float2 st; st.x = o0[i]; st.y = o1[i];
        *(float2*)&g_ctx[((size_t)(b * LL) + l) * DD + h * DH + tx*2] = st;
    }
}

// ============================================================
extern "C" void kernel_launch(void* const* d_in, const int* in_sizes, int n_in,
                              void* d_out, int out_size)
{
    const float* x      = (const float*)d_in[0];
    const float* Wq     = (const float*)d_in[1];
    const float* Wk     = (const float*)d_in[2];
    const float* Wv     = (const float*)d_in[3];
    const float* proj_k = (const float*)d_in[4];
    const float* proj_v = (const float*)d_in[5];
    const float* Wo     = (const float*)d_in[6];
    const float* bo     = (const float*)d_in[7];
    float* out = (float*)d_out;

    float *q, *xkt, *xvt, *projkt, *projvt, *keys_t, *vals, *ctx;
    cudaGetSymbolAddress((void**)&q,      g_q);
    cudaGetSymbolAddress((void**)&xkt,    g_xkt);
    cudaGetSymbolAddress((void**)&xvt,    g_xvt);
    cudaGetSymbolAddress((void**)&projkt, g_projkt);
    cudaGetSymbolAddress((void**)&projvt, g_projvt);
    cudaGetSymbolAddress((void**)&keys_t, g_keys_t);
    cudaGetSymbolAddress((void**)&vals,   g_vals);
    cudaGetSymbolAddress((void**)&ctx,    g_ctx);

    cudaFuncSetAttribute(gemm_fp16x2<false>, cudaFuncAttributeMaxDynamicSharedMemorySize, GEMM_SMEM);
    cudaFuncSetAttribute(gemm_fp16x2<true>,  cudaFuncAttributeMaxDynamicSharedMemorySize, GEMM_SMEM);
    cudaFuncSetAttribute(attn_kernel, cudaFuncAttributeMaxDynamicSharedMemorySize, ATTN_SMEM);

    // proj_k / proj_v -> transposed [K,L]
    transpose_proj<<<dim3(KK/32, LL/32, 2), dim3(32, 8)>>>(proj_k, proj_v, projkt, projvt);

    // q = x @ Wq^T
    gemm_fp16x2<false><<<dim3(DD/128, MROWS/128, 1), 256, GEMM_SMEM>>>(
        x, 0, DD, Wq, 0, DD, q, 0, DD, nullptr, DD);

    // xk_t[b] = Wk x_b^T : [1024, 2048]
    gemm_fp16x2<false><<<dim3(LL/128, DD/128, BB), 256, GEMM_SMEM>>>(
        Wk, 0, DD, x, (long)LL*DD, DD, xkt, (long)DD*LL, LL, nullptr, DD);

    // xv_t[b]
    gemm_fp16x2<false><<<dim3(LL/128, DD/128, BB), 256, GEMM_SMEM>>>(
        Wv, 0, DD, x, (long)LL*DD, DD, xvt, (long)DD*LL, LL, nullptr, DD);

    // keys_t[b][d][k] = sum_l xkt[d,l] * projkt[k,l]
    gemm_fp16x2<false><<<dim3(KK/128, DD/128, BB), 256, GEMM_SMEM>>>(
        xkt, (long)DD*LL, LL, projkt, 0, LL, keys_t, (long)DD*KK, KK, nullptr, LL);

    // vals[b][k][d] = sum_l projvt[k,l] * xvt[d,l]
    gemm_fp16x2<false><<<dim3(DD/128, KK/128, BB), 256, GEMM_SMEM>>>(
        projvt, 0, LL, xvt, (long)DD*LL, LL, vals, (long)KK*DD, DD, nullptr, LL);

    // attention core
    attn_kernel<<<dim3(LL/64, HH, BB), 256, ATTN_SMEM>>>();

    // out = ctx @ Wo^T + bo
    gemm_fp16x2<true><<<dim3(DD/128, MROWS/128, 1), 256, GEMM_SMEM>>>(
        ctx, 0, DD, Wo, 0, DD, out, 0, DD, bo, DD);
}